// round 3
// baseline (speedup 1.0000x reference)
#include <cuda_runtime.h>

#define N_TOT 262144
#define FGN   2048
#define NBINS 2049   // 2048 query bins + overflow slot

// Persistent scratch (device globals are the allowed scratch mechanism).
__device__ float g_sorted_fg[FGN];
// bins: [0]=H1_bg [1]=H2_bg [2]=S1_bg [3]=S2_bg [4]=H1_fg [5]=H2_fg [6]=S1_fg [7]=S2_fg
__device__ float g_bins[8][NBINS];

// ---------------------------------------------------------------------------
// Zero the bin arrays (must run every launch: state persists across replays).
// ---------------------------------------------------------------------------
__global__ void kZero() {
    int i = blockIdx.x * blockDim.x + threadIdx.x;
    if (i < 8 * NBINS) ((float*)g_bins)[i] = 0.0f;
}

// ---------------------------------------------------------------------------
// Rank-sort the 2048 fg logits: one warp per element, count smaller elements
// (stable tie-break by index), scatter into g_sorted_fg.
// ---------------------------------------------------------------------------
__global__ void kRank(const float* __restrict__ logits) {
    int gw   = (blockIdx.x * blockDim.x + threadIdx.x) >> 5;
    int lane = threadIdx.x & 31;
    if (gw >= FGN) return;
    float v = __ldg(&logits[gw]);
    int cnt = 0;
#pragma unroll 4
    for (int j = lane; j < FGN; j += 32) {
        float u = __ldg(&logits[j]);
        cnt += (u < v) || (u == v && j < gw);
    }
#pragma unroll
    for (int o = 16; o; o >>= 1) cnt += __shfl_xor_sync(0xffffffffu, cnt, o);
    if (lane == 0) g_sorted_fg[cnt] = v;
}

// ---------------------------------------------------------------------------
// Binning pass: 4 elements per thread (float4). For each logit v, find
// i1 = upper_bound(v-1), i2 = lower_bound(v+1) in the sorted fg table and
// accumulate {count, (v+1)/2} at both boundary bins.
// ---------------------------------------------------------------------------
__device__ __forceinline__ void binOne(const float* __restrict__ s,
                                       float v, int base) {
    float x1 = v - 1.0f;
    float x2 = v + 1.0f;

    // i1 = first index with s[i] > x1
    int l = 0, h = FGN;
#pragma unroll
    for (int it = 0; it < 11; it++) {
        int m = (l + h) >> 1;
        if (s[m] > x1) h = m; else l = m + 1;
        if (l >= h) break;
    }
    int i1 = l;

    // i2 = first index with s[i] >= x2 (search starts at i1)
    h = FGN;
    while (l < h) {
        int m = (l + h) >> 1;
        if (s[m] >= x2) h = m; else l = m + 1;
    }
    int i2 = l;

    float w = 0.5f * (v + 1.0f);
    atomicAdd(&g_bins[base + 0][i1], 1.0f);
    atomicAdd(&g_bins[base + 2][i1], w);
    atomicAdd(&g_bins[base + 1][i2], 1.0f);
    atomicAdd(&g_bins[base + 3][i2], w);
}

__global__ void kBins(const float4* __restrict__ logits4,
                      const int4*   __restrict__ targets4) {
    __shared__ float s[FGN];
    for (int j = threadIdx.x; j < FGN; j += blockDim.x)
        s[j] = g_sorted_fg[j];
    __syncthreads();

    int c = blockIdx.x * blockDim.x + threadIdx.x;   // chunk index (4 elems)
    if (c >= N_TOT / 4) return;
    float4 v = __ldg(&logits4[c]);
    bool isFg = (c < FGN / 4);                        // chunk entirely fg or bg

    if (isFg) {
        binOne(s, v.x, 4);
        binOne(s, v.y, 4);
        binOne(s, v.z, 4);
        binOne(s, v.w, 4);
    } else {
        int4 t = __ldg(&targets4[c]);
        if (t.x == 0) binOne(s, v.x, 0);
        if (t.y == 0) binOne(s, v.y, 0);
        if (t.z == 0) binOne(s, v.z, 0);
        if (t.w == 0) binOne(s, v.w, 0);
    }
}

// ---------------------------------------------------------------------------
// Finisher (1 block, 1024 threads): 6 inclusive scans over 2048 bins,
// per-query a/b reconstruction, running-max scan, sum reduce -> metric.
// Shared budget: 6 * 2048 * 4B = 48KB (static limit).
// ---------------------------------------------------------------------------
__device__ __forceinline__ float* scan_add(float* in, float* out) {
    int t = threadIdx.x;
    for (int d = 1; d < FGN; d <<= 1) {
        __syncthreads();
#pragma unroll
        for (int k = 0; k < 2; k++) {
            int i = t + k * 1024;
            float x = in[i];
            if (i >= d) x += in[i - d];
            out[i] = x;
        }
        float* tmp = in; in = out; out = tmp;
    }
    __syncthreads();
    return in;  // final result
}

__device__ __forceinline__ float* scan_max(float* in, float* out) {
    int t = threadIdx.x;
    for (int d = 1; d < FGN; d <<= 1) {
        __syncthreads();
#pragma unroll
        for (int k = 0; k < 2; k++) {
            int i = t + k * 1024;
            float x = in[i];
            if (i >= d) x = fmaxf(x, in[i - d]);
            out[i] = x;
        }
        float* tmp = in; in = out; out = tmp;
    }
    __syncthreads();
    return in;
}

__global__ void kFinal(float* __restrict__ out) {
    __shared__ float bufA[FGN];
    __shared__ float bufB[FGN];
    __shared__ float P1[FGN];
    __shared__ float Mm[FGN];
    __shared__ float bArr[FGN];
    __shared__ float curA[FGN];
    int t = threadIdx.x;

    // ---------- BG set ----------
    for (int i = t; i < FGN; i += 1024) bufA[i] = g_bins[0][i];
    float* r = scan_add(bufA, bufB);
    for (int i = t; i < FGN; i += 1024) P1[i] = r[i];
    __syncthreads();

    for (int i = t; i < FGN; i += 1024) bufA[i] = g_bins[0][i] - g_bins[1][i];
    r = scan_add(bufA, bufB);
    for (int i = t; i < FGN; i += 1024) Mm[i] = r[i];
    __syncthreads();

    for (int i = t; i < FGN; i += 1024) bufA[i] = g_bins[2][i] - g_bins[3][i];
    r = scan_add(bufA, bufB);
    float Nb = P1[FGN - 1] + g_bins[0][FGN];  // total contributing bg
    for (int i = t; i < FGN; i += 1024) {
        float fv = g_sorted_fg[i];
        bArr[i] = (Nb - P1[i]) + r[i] - 0.5f * fv * Mm[i];
    }
    __syncthreads();

    // ---------- FG set ----------
    for (int i = t; i < FGN; i += 1024) bufA[i] = g_bins[4][i];
    r = scan_add(bufA, bufB);
    for (int i = t; i < FGN; i += 1024) P1[i] = r[i];
    __syncthreads();

    for (int i = t; i < FGN; i += 1024) bufA[i] = g_bins[4][i] - g_bins[5][i];
    r = scan_add(bufA, bufB);
    for (int i = t; i < FGN; i += 1024) Mm[i] = r[i];
    __syncthreads();

    for (int i = t; i < FGN; i += 1024) bufA[i] = g_bins[6][i] - g_bins[7][i];
    r = scan_add(bufA, bufB);
    float Na = P1[FGN - 1] + g_bins[4][FGN];
    for (int i = t; i < FGN; i += 1024) {
        float fv = g_sorted_fg[i];
        float a  = (Na - P1[i]) + r[i] - 0.5f * fv * Mm[i] + 0.5f;
        curA[i]  = a / (a + bArr[i]);
    }
    __syncthreads();

    // ---------- running max over ascending-sorted queries ----------
    for (int i = t; i < FGN; i += 1024) bufA[i] = curA[i];
    r = scan_max(bufA, bufB);

    // ---------- sum reduce ----------
    float sloc = r[t] + r[t + 1024];
    __syncthreads();
    P1[t] = sloc;
    __syncthreads();
    for (int o = 512; o; o >>= 1) {
        if (t < o) P1[t] += P1[t + o];
        __syncthreads();
    }
    if (t == 0) out[0] = 1.0f - P1[0] / (float)FGN;
}

// ---------------------------------------------------------------------------
extern "C" void kernel_launch(void* const* d_in, const int* in_sizes, int n_in,
                              void* d_out, int out_size) {
    const float* logits  = (const float*)d_in[0];
    const int*   targets = (const int*)d_in[1];
    float*       out     = (float*)d_out;

    kZero<<<(8 * NBINS + 255) / 256, 256>>>();
    kRank<<<(FGN * 32) / 256, 256>>>(logits);
    kBins<<<(N_TOT / 4) / 256, 256>>>((const float4*)logits, (const int4*)targets);
    kFinal<<<1, 1024>>>(out);
}

// round 5
// speedup vs baseline: 1.2159x; 1.2159x over previous
#include <cuda_runtime.h>

#define N_TOT 262144
#define FGN   2048
#define NBINS 2049   // 2048 query bins + overflow slot

// Persistent scratch (device globals are the allowed scratch mechanism).
__device__ float g_sorted_fg[FGN];
// bins: [0]=H1_bg [1]=H2_bg [2]=S1_bg [3]=S2_bg [4]=H1_fg [5]=H2_fg [6]=S1_fg [7]=S2_fg
__device__ float g_bins[8][NBINS];

// ---------------------------------------------------------------------------
// Rank-sort the 2048 fg logits (one warp per element), and zero the bin
// arrays (must happen every launch: device state persists across replays).
// ---------------------------------------------------------------------------
__global__ void kRank(const float* __restrict__ logits) {
    int tidG = blockIdx.x * blockDim.x + threadIdx.x;
    // fold in kZero: first 16392 threads clear the bins
    if (tidG < 8 * NBINS) ((float*)g_bins)[tidG] = 0.0f;

    int gw   = tidG >> 5;
    int lane = threadIdx.x & 31;
    if (gw >= FGN) return;
    float v = __ldg(&logits[gw]);
    int cnt = 0;
#pragma unroll 4
    for (int j = lane; j < FGN; j += 32) {
        float u = __ldg(&logits[j]);
        cnt += (u < v) || (u == v && j < gw);
    }
#pragma unroll
    for (int o = 16; o; o >>= 1) cnt += __shfl_xor_sync(0xffffffffu, cnt, o);
    if (lane == 0) g_sorted_fg[cnt] = v;
}

// ---------------------------------------------------------------------------
// Binning pass: 4 elements per thread (float4). For each logit v, find
// i1 = upper_bound(v-1), i2 = lower_bound(v+1) in the sorted fg table and
// accumulate {count, (v+1)/2} at both boundary bins.
// ---------------------------------------------------------------------------
__device__ __forceinline__ void binOne(const float* __restrict__ s,
                                       float v, int base) {
    float x1 = v - 1.0f;
    float x2 = v + 1.0f;

    // i1 = first index with s[i] > x1
    int l = 0, h = FGN;
#pragma unroll
    for (int it = 0; it < 11; it++) {
        int m = (l + h) >> 1;
        if (s[m] > x1) h = m; else l = m + 1;
        if (l >= h) break;
    }
    int i1 = l;

    // i2 = first index with s[i] >= x2 (search starts at i1)
    h = FGN;
    while (l < h) {
        int m = (l + h) >> 1;
        if (s[m] >= x2) h = m; else l = m + 1;
    }
    int i2 = l;

    float w = 0.5f * (v + 1.0f);
    atomicAdd(&g_bins[base + 0][i1], 1.0f);
    atomicAdd(&g_bins[base + 2][i1], w);
    atomicAdd(&g_bins[base + 1][i2], 1.0f);
    atomicAdd(&g_bins[base + 3][i2], w);
}

__global__ void kBins(const float4* __restrict__ logits4,
                      const int4*   __restrict__ targets4) {
    __shared__ float s[FGN];
    for (int j = threadIdx.x; j < FGN; j += blockDim.x)
        s[j] = g_sorted_fg[j];
    __syncthreads();

    int c = blockIdx.x * blockDim.x + threadIdx.x;   // chunk index (4 elems)
    if (c >= N_TOT / 4) return;
    float4 v = __ldg(&logits4[c]);
    bool isFg = (c < FGN / 4);                        // chunk entirely fg or bg

    if (isFg) {
        binOne(s, v.x, 4);
        binOne(s, v.y, 4);
        binOne(s, v.z, 4);
        binOne(s, v.w, 4);
    } else {
        int4 t = __ldg(&targets4[c]);
        if (t.x == 0) binOne(s, v.x, 0);
        if (t.y == 0) binOne(s, v.y, 0);
        if (t.z == 0) binOne(s, v.z, 0);
        if (t.w == 0) binOne(s, v.w, 0);
    }
}

// ---------------------------------------------------------------------------
// Finisher (1 block, 1024 threads). Each thread owns 2 consecutive bins of
// all 6 scan arrays in registers. Hierarchical scans: warp shuffle scan
// (no barriers) + one cross-warp level where warps 0..5 handle one array
// each in parallel. 6 barriers total (vs ~80 in the Hillis-Steele version).
// ---------------------------------------------------------------------------
__device__ __forceinline__ float wscan_add(float p, int lane) {
    float s = p;
#pragma unroll
    for (int o = 1; o < 32; o <<= 1) {
        float n = __shfl_up_sync(0xffffffffu, s, o);
        if (lane >= o) s += n;
    }
    return s;
}
__device__ __forceinline__ float wscan_max(float p, int lane) {
    float s = p;
#pragma unroll
    for (int o = 1; o < 32; o <<= 1) {
        float n = __shfl_up_sync(0xffffffffu, s, o);
        if (lane >= o) s = fmaxf(s, n);
    }
    return s;
}

__global__ void kFinal(float* __restrict__ out) {
    __shared__ float agg[7][33];
    __shared__ float totals[8];
    int t    = threadIdx.x;
    int lane = t & 31;
    int wid  = t >> 5;          // 32 warps
    int i0 = 2 * t, i1 = 2 * t + 1;

    // Load raw bins (2 per array slot per thread).
    float h1b0 = g_bins[0][i0], h1b1 = g_bins[0][i1];
    float h2b0 = g_bins[1][i0], h2b1 = g_bins[1][i1];
    float s1b0 = g_bins[2][i0], s1b1 = g_bins[2][i1];
    float s2b0 = g_bins[3][i0], s2b1 = g_bins[3][i1];
    float h1f0 = g_bins[4][i0], h1f1 = g_bins[4][i1];
    float h2f0 = g_bins[5][i0], h2f1 = g_bins[5][i1];
    float s1f0 = g_bins[6][i0], s1f1 = g_bins[6][i1];
    float s2f0 = g_bins[7][i0], s2f1 = g_bins[7][i1];

    // 6 scan inputs: P1bg, Mbg, Sbg, P1fg, Mfg, Sfg  (second elem per pair)
    float a0_0 = h1b0,        a0_1 = h1b1;
    float a1_0 = h1b0 - h2b0, a1_1 = h1b1 - h2b1;
    float a2_0 = s1b0 - s2b0, a2_1 = s1b1 - s2b1;
    float a3_0 = h1f0,        a3_1 = h1f1;
    float a4_0 = h1f0 - h2f0, a4_1 = h1f1 - h2f1;
    float a5_0 = s1f0 - s2f0, a5_1 = s1f1 - s2f1;

    // Level 1: warp-scan of pair sums, all 6 arrays (register-resident).
    float sc0 = wscan_add(a0_0 + a0_1, lane);
    float sc1 = wscan_add(a1_0 + a1_1, lane);
    float sc2 = wscan_add(a2_0 + a2_1, lane);
    float sc3 = wscan_add(a3_0 + a3_1, lane);
    float sc4 = wscan_add(a4_0 + a4_1, lane);
    float sc5 = wscan_add(a5_0 + a5_1, lane);
    if (lane == 31) {
        agg[0][wid] = sc0; agg[1][wid] = sc1; agg[2][wid] = sc2;
        agg[3][wid] = sc3; agg[4][wid] = sc4; agg[5][wid] = sc5;
    }
    __syncthreads();                                   // B1

    // Level 2: warps 0..5 scan the 32 warp-totals of array `wid` in parallel.
    if (wid < 6) {
        float v = agg[wid][lane];
        float s = wscan_add(v, lane);
        agg[wid][lane] = s;                            // inclusive totals
        if (lane == 31) totals[wid] = s;               // grand total
    }
    __syncthreads();                                   // B2

    float o0 = wid ? agg[0][wid - 1] : 0.0f;
    float o1 = wid ? agg[1][wid - 1] : 0.0f;
    float o2 = wid ? agg[2][wid - 1] : 0.0f;
    float o3 = wid ? agg[3][wid - 1] : 0.0f;
    float o4 = wid ? agg[4][wid - 1] : 0.0f;
    float o5 = wid ? agg[5][wid - 1] : 0.0f;

    // Inclusive prefixes for both owned elements.
    float P1b_1 = o0 + sc0, P1b_0 = P1b_1 - a0_1;
    float Mb_1  = o1 + sc1, Mb_0  = Mb_1  - a1_1;
    float Sb_1  = o2 + sc2, Sb_0  = Sb_1  - a2_1;
    float P1f_1 = o3 + sc3, P1f_0 = P1f_1 - a3_1;
    float Mf_1  = o4 + sc4, Mf_0  = Mf_1  - a4_1;
    float Sf_1  = o5 + sc5, Sf_0  = Sf_1  - a5_1;

    float Nb = totals[0] + g_bins[0][FGN];   // + overflow slot
    float Na = totals[3] + g_bins[4][FGN];

    float fv0 = g_sorted_fg[i0];
    float fv1 = g_sorted_fg[i1];

    float b0 = (Nb - P1b_0) + Sb_0 - 0.5f * fv0 * Mb_0;
    float b1 = (Nb - P1b_1) + Sb_1 - 0.5f * fv1 * Mb_1;
    float A0 = (Na - P1f_0) + Sf_0 - 0.5f * fv0 * Mf_0 + 0.5f;
    float A1 = (Na - P1f_1) + Sf_1 - 0.5f * fv1 * Mf_1 + 0.5f;
    float cur0 = A0 / (A0 + b0);
    float cur1 = A1 / (A1 + b1);

    // Running max over ascending-sorted queries (hierarchical max-scan).
    float pm = fmaxf(cur0, cur1);
    float sm = wscan_max(pm, lane);                    // inclusive pair-max scan
    if (lane == 31) agg[6][wid] = sm;
    __syncthreads();                                   // B3
    if (wid == 0) {
        float v = agg[6][lane];
        agg[6][lane] = wscan_max(v, lane);             // inclusive
    }
    __syncthreads();                                   // B4

    float offm = wid ? agg[6][wid - 1] : 0.0f;
    float prevInWarp = __shfl_up_sync(0xffffffffu, sm, 1);
    float warpExcl = (lane == 0) ? 0.0f : prevInWarp;
    float base = fmaxf(offm, warpExcl);
    float m0 = fmaxf(base, cur0);
    float m1 = fmaxf(m0, cur1);

    __syncthreads();                                   // B5 (protect agg[6] reuse)

    // Sum reduce of the 2048 running-max values.
    float sl = m0 + m1;
#pragma unroll
    for (int o = 16; o; o >>= 1) sl += __shfl_xor_sync(0xffffffffu, sl, o);
    if (lane == 0) agg[6][wid] = sl;
    __syncthreads();                                   // B6
    if (wid == 0) {
        float v = agg[6][lane];
#pragma unroll
        for (int o = 16; o; o >>= 1) v += __shfl_xor_sync(0xffffffffu, v, o);
        if (lane == 0) out[0] = 1.0f - v / (float)FGN;
    }
}

// ---------------------------------------------------------------------------
extern "C" void kernel_launch(void* const* d_in, const int* in_sizes, int n_in,
                              void* d_out, int out_size) {
    const float* logits  = (const float*)d_in[0];
    const int*   targets = (const int*)d_in[1];
    float*       out     = (float*)d_out;

    kRank<<<(FGN * 32) / 256, 256>>>(logits);
    kBins<<<(N_TOT / 4) / 256, 256>>>((const float4*)logits, (const int4*)targets);
    kFinal<<<1, 1024>>>(out);
}